// round 12
// baseline (speedup 1.0000x reference)
#include <cuda_runtime.h>
#include <cuda_bf16.h>
#include <cstdint>
#include <math.h>

// Causal self-attention B=4,S=2048,D=1024 fp32.
// HYBRID: HMMA (mma.sync bf16 3-term split, round-6 proven config) on 13/16 of
// N-columns + fp32 SIMT core (round-1 proven layout) on 3/16, stacking the
// tensor pipe (311 TF/s ceiling, confirmed) with the idle FMA pipe.

#define B_  4
#define S_  2048
#define D_  1024
#define TM  128
#define TN  64
#define BK  32

// HMMA per-stage smem layout (bytes) — round-6 verbatim
#define A_STRIDE_B    80
#define B_NT_STRIDE_B 80
#define B_NN_STRIDE_B 144
#define OFF_AH 0
#define OFF_AL 10240
#define OFF_BH 20480
#define OFF_BL 26240
#define STAGE_BYTES 32000
#define SMEM_TOTAL  (2 * STAGE_BYTES)   // 64000 B dynamic smem

// fp32 SIMT core (128x64 tile, BK=16) — overlays same dynamic smem
#define FBK 16
#define FA_LD 132               // floats per k-row for A (128+4)
#define FB_LD 68                // floats per k-row for B (64+4)
#define FB_OFF_F (FBK * FA_LD)  // float offset of Bs

// which 64-col blocks go to the fp32 core (3/16 = 18.75%)
#define FP32_OWNS(bx) (((bx) & 15) == 5 || ((bx) & 15) == 10 || ((bx) & 15) == 15)

// ---------------- scratch --------------------------------------------------
__device__ alignas(256) __nv_bfloat16 g_Xhi[(size_t)B_*S_*D_], g_Xlo[(size_t)B_*S_*D_];
__device__ alignas(256) __nv_bfloat16 g_Whi[3][(size_t)D_*D_], g_Wlo[3][(size_t)D_*D_];
__device__ alignas(256) __nv_bfloat16 g_Qhi[(size_t)B_*S_*D_], g_Qlo[(size_t)B_*S_*D_];
__device__ alignas(256) __nv_bfloat16 g_Khi[(size_t)B_*S_*D_], g_Klo[(size_t)B_*S_*D_];
__device__ alignas(256) __nv_bfloat16 g_Vhi[(size_t)B_*S_*D_], g_Vlo[(size_t)B_*S_*D_];
__device__ alignas(256) float         g_S[(size_t)B_*S_*S_];
__device__ alignas(256) __nv_bfloat16 g_Phi[(size_t)B_*S_*S_], g_Plo[(size_t)B_*S_*S_];

// ---------------- PTX helpers ----------------------------------------------
__device__ __forceinline__ uint32_t smem_u32(const void* p) {
    uint32_t a;
    asm("{ .reg .u64 t; cvta.to.shared.u64 t, %1; cvt.u32.u64 %0, t; }" : "=r"(a) : "l"(p));
    return a;
}
__device__ __forceinline__ void cp16(uint32_t dst, const void* src) {
    asm volatile("cp.async.cg.shared.global [%0], [%1], 16;" :: "r"(dst), "l"(src));
}
__device__ __forceinline__ void cp_commit() {
    asm volatile("cp.async.commit_group;" ::: "memory");
}
template <int N>
__device__ __forceinline__ void cp_wait() {
    asm volatile("cp.async.wait_group %0;" :: "n"(N) : "memory");
}
__device__ __forceinline__ void ldm_x4(uint32_t* r, uint32_t addr) {
    asm volatile("ldmatrix.sync.aligned.m8n8.x4.shared.b16 {%0,%1,%2,%3}, [%4];"
                 : "=r"(r[0]), "=r"(r[1]), "=r"(r[2]), "=r"(r[3]) : "r"(addr));
}
__device__ __forceinline__ void ldm_x2(uint32_t* r, uint32_t addr) {
    asm volatile("ldmatrix.sync.aligned.m8n8.x2.shared.b16 {%0,%1}, [%2];"
                 : "=r"(r[0]), "=r"(r[1]) : "r"(addr));
}
__device__ __forceinline__ void ldm_x2_t(uint32_t* r, uint32_t addr) {
    asm volatile("ldmatrix.sync.aligned.m8n8.x2.trans.shared.b16 {%0,%1}, [%2];"
                 : "=r"(r[0]), "=r"(r[1]) : "r"(addr));
}
__device__ __forceinline__ void mma_bf16(float* d, const uint32_t* a, const uint32_t* b) {
    asm volatile("mma.sync.aligned.m16n8k16.row.col.f32.bf16.bf16.f32 "
                 "{%0,%1,%2,%3}, {%4,%5,%6,%7}, {%8,%9}, {%0,%1,%2,%3};"
                 : "+f"(d[0]), "+f"(d[1]), "+f"(d[2]), "+f"(d[3])
                 : "r"(a[0]), "r"(a[1]), "r"(a[2]), "r"(a[3]), "r"(b[0]), "r"(b[1]));
}

// ---------------- HMMA cp.async staging (round-6 verbatim) ------------------
__device__ __forceinline__ void stage_A_cp(uint32_t dst, const __nv_bfloat16* src,
                                           int ld, int k0) {
    const int tid = threadIdx.x;
#pragma unroll
    for (int i = 0; i < 2; ++i) {
        const int s = tid + i * 256;
        const int row = s >> 2, seg = s & 3;
        cp16(dst + row * A_STRIDE_B + seg * 16, src + (size_t)row * ld + k0 + seg * 8);
    }
}
__device__ __forceinline__ void stage_B_nt_cp(uint32_t dst, const __nv_bfloat16* src,
                                              int ld, int k0) {
    const int s = threadIdx.x;
    const int row = s >> 2, seg = s & 3;
    cp16(dst + row * B_NT_STRIDE_B + seg * 16, src + (size_t)row * ld + k0 + seg * 8);
}
__device__ __forceinline__ void stage_B_nn_cp(uint32_t dst, const __nv_bfloat16* src,
                                              int ld, int k0) {
    const int s = threadIdx.x;
    const int row = s >> 3, seg = s & 7;
    cp16(dst + row * B_NN_STRIDE_B + seg * 16, src + (size_t)(k0 + row) * ld + seg * 8);
}

// ---------------- HMMA 3-term pipelined mainloop (round-6 verbatim) ---------
__device__ __forceinline__ void mma_mainloop(
    uint32_t sb, const __nv_bfloat16* Ah, const __nv_bfloat16* Al,
    const __nv_bfloat16* Bh, const __nv_bfloat16* Bl,
    int lda, int ldb, int nchunks, bool nnB, float acc[2][4][4])
{
    const int tid = threadIdx.x;
    const int lane = tid & 31, w = tid >> 5;
    const int wm = w & 3, wn = w >> 2;

    const uint32_t a_off   = (uint32_t)(wm * 32 + (lane & 15)) * A_STRIDE_B + ((lane >> 4) << 3) * 2;
    const uint32_t bnt_off = (uint32_t)(wn * 32 + (lane & 7)) * B_NT_STRIDE_B + ((lane >> 3) & 1) * 16;
    const uint32_t bnn_off = (uint32_t)(lane & 15) * B_NN_STRIDE_B + (uint32_t)(wn * 32) * 2;

    auto issue = [&](int c) {
        const uint32_t buf = sb + (uint32_t)(c & 1) * STAGE_BYTES;
        const int k0 = c * BK;
        stage_A_cp(buf + OFF_AH, Ah, lda, k0);
        stage_A_cp(buf + OFF_AL, Al, lda, k0);
        if (nnB) { stage_B_nn_cp(buf + OFF_BH, Bh, ldb, k0);
                   stage_B_nn_cp(buf + OFF_BL, Bl, ldb, k0); }
        else     { stage_B_nt_cp(buf + OFF_BH, Bh, ldb, k0);
                   stage_B_nt_cp(buf + OFF_BL, Bl, ldb, k0); }
        cp_commit();
    };

    issue(0);
    for (int c = 0; c < nchunks; ++c) {
        if (c + 1 < nchunks) { issue(c + 1); cp_wait<1>(); }
        else                 { cp_wait<0>(); }
        __syncthreads();

        const uint32_t buf = sb + (uint32_t)(c & 1) * STAGE_BYTES;
#pragma unroll
        for (int ks = 0; ks < 2; ++ks) {
            const uint32_t kb = ks * 32;
            uint32_t ah[2][4], al[2][4], bh[4][2], bl[4][2];
#pragma unroll
            for (int tm = 0; tm < 2; ++tm) {
                ldm_x4(ah[tm], buf + OFF_AH + a_off + tm * (16 * A_STRIDE_B) + kb);
                ldm_x4(al[tm], buf + OFF_AL + a_off + tm * (16 * A_STRIDE_B) + kb);
            }
            if (nnB) {
#pragma unroll
                for (int tn = 0; tn < 4; ++tn) {
                    ldm_x2_t(bh[tn], buf + OFF_BH + bnn_off + kb * (B_NN_STRIDE_B / 2) + tn * 16);
                    ldm_x2_t(bl[tn], buf + OFF_BL + bnn_off + kb * (B_NN_STRIDE_B / 2) + tn * 16);
                }
            } else {
#pragma unroll
                for (int tn = 0; tn < 4; ++tn) {
                    ldm_x2(bh[tn], buf + OFF_BH + bnt_off + tn * (8 * B_NT_STRIDE_B) + kb);
                    ldm_x2(bl[tn], buf + OFF_BL + bnt_off + tn * (8 * B_NT_STRIDE_B) + kb);
                }
            }
#pragma unroll
            for (int tm = 0; tm < 2; ++tm)
#pragma unroll
                for (int tn = 0; tn < 4; ++tn) {
                    mma_bf16(acc[tm][tn], ah[tm], bh[tn]);
                    mma_bf16(acc[tm][tn], ah[tm], bl[tn]);
                    mma_bf16(acc[tm][tn], al[tm], bh[tn]);
                }
        }
        __syncthreads();
    }
}

// ---------------- fp32 SIMT core (128x64, BK=16; round-1 layout) ------------
__device__ __forceinline__ float rec1(const __nv_bfloat16* h, const __nv_bfloat16* l,
                                      size_t idx) {
    return __bfloat162float(h[idx]) + __bfloat162float(l[idx]);
}
// reconstruct 4 consecutive elements via 8B loads
__device__ __forceinline__ void rec4(const __nv_bfloat16* h, const __nv_bfloat16* l,
                                     size_t idx, float* out) {
    const uint2 uh = *reinterpret_cast<const uint2*>(h + idx);
    const uint2 ul = *reinterpret_cast<const uint2*>(l + idx);
    const float2 h0 = __bfloat1622float2(*reinterpret_cast<const __nv_bfloat162*>(&uh.x));
    const float2 h1 = __bfloat1622float2(*reinterpret_cast<const __nv_bfloat162*>(&uh.y));
    const float2 l0 = __bfloat1622float2(*reinterpret_cast<const __nv_bfloat162*>(&ul.x));
    const float2 l1 = __bfloat1622float2(*reinterpret_cast<const __nv_bfloat162*>(&ul.y));
    out[0] = h0.x + l0.x; out[1] = h0.y + l0.y;
    out[2] = h1.x + l1.x; out[3] = h1.y + l1.y;
}

// A [128,K] K-contig (hi/lo); B NT: [64,K]; B NN: [K,64] (base pre-offset to col 0)
__device__ __forceinline__ void f32_mainloop(
    float* smf, const __nv_bfloat16* Ah, const __nv_bfloat16* Al,
    const __nv_bfloat16* Bh, const __nv_bfloat16* Bl,
    int lda, int ldb, int nchunks, bool nnB, float acc[8][4])
{
    const int tid = threadIdx.x;
    const int tx = tid & 15, ty = tid >> 4;
    float* As = smf;              // [FBK][FA_LD]
    float* Bs = smf + FB_OFF_F;   // [FBK][FB_LD]

    for (int c = 0; c < nchunks; ++c) {
        const int k0 = c * FBK;
        // A: 128 rows x 16 k
        {
            const int lk = (tid & 3) * 4;
#pragma unroll
            for (int it = 0; it < 2; ++it) {
                const int row = (tid >> 2) + it * 64;
                float v[4];
                rec4(Ah, Al, (size_t)row * lda + k0 + lk, v);
#pragma unroll
                for (int j = 0; j < 4; ++j) As[(lk + j) * FA_LD + row] = v[j];
            }
        }
        // B
        if (nnB) {
            // [k,64]: 16 rows x 64 cols
            const int kk = tid >> 4, cn = (tid & 15) * 4;
            float v[4];
            rec4(Bh, Bl, (size_t)(k0 + kk) * ldb + cn, v);
#pragma unroll
            for (int j = 0; j < 4; ++j) Bs[kk * FB_LD + cn + j] = v[j];
        } else {
            // [64,K]: 64 rows x 16 k
            if (tid < 256) {
                const int row = tid >> 2, lk = (tid & 3) * 4;
                float v[4];
                rec4(Bh, Bl, (size_t)row * ldb + k0 + lk, v);
#pragma unroll
                for (int j = 0; j < 4; ++j) Bs[(lk + j) * FB_LD + row] = v[j];
            }
        }
        __syncthreads();
#pragma unroll
        for (int k = 0; k < FBK; ++k) {
            const float4 a0 = *reinterpret_cast<const float4*>(&As[k * FA_LD + ty * 4]);
            const float4 a1 = *reinterpret_cast<const float4*>(&As[k * FA_LD + 64 + ty * 4]);
            const float4 b0 = *reinterpret_cast<const float4*>(&Bs[k * FB_LD + tx * 4]);
            const float ra[8] = {a0.x, a0.y, a0.z, a0.w, a1.x, a1.y, a1.z, a1.w};
            const float rb[4] = {b0.x, b0.y, b0.z, b0.w};
#pragma unroll
            for (int i = 0; i < 8; ++i)
#pragma unroll
                for (int j = 0; j < 4; ++j)
                    acc[i][j] = fmaf(ra[i], rb[j], acc[i][j]);
        }
        __syncthreads();
    }
}

// ---------------- kernels ---------------------------------------------------
__global__ void dummy_kernel() {}

__global__ void __launch_bounds__(256) split_kernel(
    const float* __restrict__ X, const float* __restrict__ WQ,
    const float* __restrict__ WK, const float* __restrict__ WV)
{
    const int nX4 = (B_ * S_ * D_) / 4;
    const int nW4 = (D_ * D_) / 4;
    const int i = blockIdx.x * 256 + threadIdx.x;

    const float* src; __nv_bfloat16 *hi, *lo; int idx;
    if (i < nX4)                { src = X;  hi = g_Xhi;    lo = g_Xlo;    idx = i; }
    else if (i < nX4 + nW4)     { src = WQ; hi = g_Whi[0]; lo = g_Wlo[0]; idx = i - nX4; }
    else if (i < nX4 + 2 * nW4) { src = WK; hi = g_Whi[1]; lo = g_Wlo[1]; idx = i - nX4 - nW4; }
    else                        { src = WV; hi = g_Whi[2]; lo = g_Wlo[2]; idx = i - nX4 - 2 * nW4; }

    const float4 v = reinterpret_cast<const float4*>(src)[idx];
    __nv_bfloat16 h[4], l[4];
    const float f[4] = {v.x, v.y, v.z, v.w};
#pragma unroll
    for (int j = 0; j < 4; ++j) {
        h[j] = __float2bfloat16(f[j]);
        l[j] = __float2bfloat16(f[j] - __bfloat162float(h[j]));
    }
    *reinterpret_cast<uint2*>(hi + (size_t)idx * 4) = *reinterpret_cast<uint2*>(h);
    *reinterpret_cast<uint2*>(lo + (size_t)idx * 4) = *reinterpret_cast<uint2*>(l);
}

__global__ void __launch_bounds__(256, 2) qkv_kernel() {
    extern __shared__ __align__(16) char smdyn[];
    const int z  = blockIdx.z;
    const int m0 = blockIdx.y * TM;
    const int bx = blockIdx.x;
    const int n0 = bx * TN;
    const int lane = threadIdx.x & 31, w = threadIdx.x >> 5;

    __nv_bfloat16* oh = (z == 0) ? g_Qhi : (z == 1) ? g_Khi : g_Vhi;
    __nv_bfloat16* ol = (z == 0) ? g_Qlo : (z == 1) ? g_Klo : g_Vlo;

    if (FP32_OWNS(bx)) {
        float acc[8][4];
#pragma unroll
        for (int i = 0; i < 8; ++i)
#pragma unroll
            for (int j = 0; j < 4; ++j) acc[i][j] = 0.f;
        f32_mainloop(reinterpret_cast<float*>(smdyn),
                     g_Xhi + (size_t)m0 * D_, g_Xlo + (size_t)m0 * D_,
                     g_Whi[z] + (size_t)n0 * D_, g_Wlo[z] + (size_t)n0 * D_,
                     D_, D_, D_ / FBK, false, acc);
        const int tx = threadIdx.x & 15, ty = threadIdx.x >> 4;
#pragma unroll
        for (int i = 0; i < 8; ++i) {
            const int r = m0 + ((i < 4) ? ty * 4 + i : 64 + ty * 4 + i - 4);
            const int c = n0 + tx * 4;
#pragma unroll
            for (int g = 0; g < 2; ++g) {
                const float f0 = acc[i][2 * g + 0], f1 = acc[i][2 * g + 1];
                const __nv_bfloat16 h0 = __float2bfloat16(f0), h1 = __float2bfloat16(f1);
                __nv_bfloat162 hp; hp.x = h0; hp.y = h1;
                __nv_bfloat162 lp;
                lp.x = __float2bfloat16(f0 - __bfloat162float(h0));
                lp.y = __float2bfloat16(f1 - __bfloat162float(h1));
                const size_t o = (size_t)r * D_ + c + 2 * g;
                *reinterpret_cast<__nv_bfloat162*>(oh + o) = hp;
                *reinterpret_cast<__nv_bfloat162*>(ol + o) = lp;
            }
        }
        return;
    }

    const uint32_t sb = smem_u32(smdyn);
    float acc[2][4][4];
#pragma unroll
    for (int a = 0; a < 2; ++a)
#pragma unroll
        for (int b = 0; b < 4; ++b)
#pragma unroll
            for (int cc = 0; cc < 4; ++cc) acc[a][b][cc] = 0.f;

    mma_mainloop(sb, g_Xhi + (size_t)m0 * D_, g_Xlo + (size_t)m0 * D_,
                 g_Whi[z] + (size_t)n0 * D_, g_Wlo[z] + (size_t)n0 * D_,
                 D_, D_, D_ / BK, false, acc);

    const int wm = w & 3, wn = w >> 2;
#pragma unroll
    for (int tm = 0; tm < 2; ++tm)
#pragma unroll
        for (int tn = 0; tn < 4; ++tn) {
            const int r = m0 + wm * 32 + tm * 16 + (lane >> 2);
            const int c = n0 + wn * 32 + tn * 8 + (lane & 3) * 2;
#pragma unroll
            for (int h = 0; h < 2; ++h) {
                const float f0 = acc[tm][tn][2 * h + 0], f1 = acc[tm][tn][2 * h + 1];
                const __nv_bfloat16 h0 = __float2bfloat16(f0), h1 = __float2bfloat16(f1);
                __nv_bfloat162 hp; hp.x = h0; hp.y = h1;
                __nv_bfloat162 lp;
                lp.x = __float2bfloat16(f0 - __bfloat162float(h0));
                lp.y = __float2bfloat16(f1 - __bfloat162float(h1));
                const size_t o = (size_t)(r + h * 8) * D_ + c;
                *reinterpret_cast<__nv_bfloat162*>(oh + o) = hp;
                *reinterpret_cast<__nv_bfloat162*>(ol + o) = lp;
            }
        }
}

__global__ void __launch_bounds__(256, 2) scores_kernel() {
    const int bx = blockIdx.x, by = blockIdx.y;
    if (bx * TN > by * TM + TM - 1) return;   // fully above diagonal
    extern __shared__ __align__(16) char smdyn[];
    const int b  = blockIdx.z;
    const int q0 = by * TM;
    const int k0 = bx * TN;
    const size_t qo = ((size_t)b * S_ + q0) * D_;
    const size_t ko = ((size_t)b * S_ + k0) * D_;

    if (FP32_OWNS(bx)) {
        float acc[8][4];
#pragma unroll
        for (int i = 0; i < 8; ++i)
#pragma unroll
            for (int j = 0; j < 4; ++j) acc[i][j] = 0.f;
        f32_mainloop(reinterpret_cast<float*>(smdyn),
                     g_Qhi + qo, g_Qlo + qo, g_Khi + ko, g_Klo + ko,
                     D_, D_, D_ / FBK, false, acc);
        const int tx = threadIdx.x & 15, ty = threadIdx.x >> 4;
#pragma unroll
        for (int i = 0; i < 8; ++i) {
            const int r = q0 + ((i < 4) ? ty * 4 + i : 64 + ty * 4 + i - 4);
            const int c = k0 + tx * 4;
            float4 v;
            v.x = acc[i][0] * 0.03125f; v.y = acc[i][1] * 0.03125f;
            v.z = acc[i][2] * 0.03125f; v.w = acc[i][3] * 0.03125f;
            *reinterpret_cast<float4*>(g_S + ((size_t)b * S_ + r) * S_ + c) = v;
        }
        return;
    }

    const uint32_t sb = smem_u32(smdyn);
    float acc[2][4][4];
#pragma unroll
    for (int a = 0; a < 2; ++a)
#pragma unroll
        for (int bb = 0; bb < 4; ++bb)
#pragma unroll
            for (int cc = 0; cc < 4; ++cc) acc[a][bb][cc] = 0.f;

    mma_mainloop(sb, g_Qhi + qo, g_Qlo + qo, g_Khi + ko, g_Klo + ko,
                 D_, D_, D_ / BK, false, acc);

    const int lane = threadIdx.x & 31, w = threadIdx.x >> 5;
    const int wm = w & 3, wn = w >> 2;
#pragma unroll
    for (int tm = 0; tm < 2; ++tm)
#pragma unroll
        for (int tn = 0; tn < 4; ++tn) {
            const int r = q0 + wm * 32 + tm * 16 + (lane >> 2);
            const int c = k0 + wn * 32 + tn * 8 + (lane & 3) * 2;
#pragma unroll
            for (int h = 0; h < 2; ++h) {
                float2 v;
                v.x = acc[tm][tn][2 * h + 0] * 0.03125f;
                v.y = acc[tm][tn][2 * h + 1] * 0.03125f;
                *reinterpret_cast<float2*>(g_S + ((size_t)b * S_ + r + h * 8) * S_ + c) = v;
            }
        }
}

__global__ void __launch_bounds__(256) softmax_kernel() {
    const int q = blockIdx.x, b = blockIdx.y;
    const float* row = g_S + ((size_t)b * S_ + q) * S_;
    __nv_bfloat16* ph = g_Phi + ((size_t)b * S_ + q) * S_;
    __nv_bfloat16* pl = g_Plo + ((size_t)b * S_ + q) * S_;
    const int L = q + 1;
    const int tid = threadIdx.x;
    __shared__ float buf[S_];
    __shared__ float red[256];

    float m = -3.4e38f;
    for (int j = tid; j < L; j += 256) m = fmaxf(m, row[j]);
    red[tid] = m; __syncthreads();
    for (int s = 128; s > 0; s >>= 1) {
        if (tid < s) red[tid] = fmaxf(red[tid], red[tid + s]);
        __syncthreads();
    }
    m = red[0]; __syncthreads();

    float s = 0.f;
    for (int j = tid; j < L; j += 256) {
        const float e = expf(row[j] - m);
        buf[j] = e;
        s += e;
    }
    red[tid] = s; __syncthreads();
    for (int st = 128; st > 0; st >>= 1) {
        if (tid < st) red[tid] += red[tid + st];
        __syncthreads();
    }
    const float inv = 1.f / red[0];
    for (int j = tid; j < L; j += 256) {
        const float p = buf[j] * inv;
        const __nv_bfloat16 h = __float2bfloat16(p);
        ph[j] = h;
        pl[j] = __float2bfloat16(p - __bfloat162float(h));
    }
    const __nv_bfloat16 z = __float2bfloat16(0.f);
    for (int j = L + tid; j < S_; j += 256) { ph[j] = z; pl[j] = z; }
}

__global__ void __launch_bounds__(256, 2) pv_kernel(float* __restrict__ Out) {
    extern __shared__ __align__(16) char smdyn[];
    const int b  = blockIdx.z;
    const int q0 = blockIdx.y * TM;
    const int bx = blockIdx.x;
    const int e0 = bx * TN;
    const size_t po = ((size_t)b * S_ + q0) * S_;
    const size_t vo = (size_t)b * S_ * D_ + e0;

    if (FP32_OWNS(bx)) {
        float acc[8][4];
#pragma unroll
        for (int i = 0; i < 8; ++i)
#pragma unroll
            for (int j = 0; j < 4; ++j) acc[i][j] = 0.f;
        f32_mainloop(reinterpret_cast<float*>(smdyn),
                     g_Phi + po, g_Plo + po, g_Vhi + vo, g_Vlo + vo,
                     S_, D_, (q0 + TM) / FBK, true, acc);
        const int tx = threadIdx.x & 15, ty = threadIdx.x >> 4;
#pragma unroll
        for (int i = 0; i < 8; ++i) {
            const int r = q0 + ((i < 4) ? ty * 4 + i : 64 + ty * 4 + i - 4);
            const int c = e0 + tx * 4;
            float4 v; v.x = acc[i][0]; v.y = acc[i][1]; v.z = acc[i][2]; v.w = acc[i][3];
            *reinterpret_cast<float4*>(Out + ((size_t)b * S_ + r) * D_ + c) = v;
        }
        return;
    }

    const uint32_t sb = smem_u32(smdyn);
    const int nchunks = (q0 + TM) / BK;   // causal frontier

    float acc[2][4][4];
#pragma unroll
    for (int a = 0; a < 2; ++a)
#pragma unroll
        for (int bb = 0; bb < 4; ++bb)
#pragma unroll
            for (int cc = 0; cc < 4; ++cc) acc[a][bb][cc] = 0.f;

    mma_mainloop(sb, g_Phi + po, g_Plo + po, g_Vhi + vo, g_Vlo + vo,
                 S_, D_, nchunks, true, acc);

    const int lane = threadIdx.x & 31, w = threadIdx.x >> 5;
    const int wm = w & 3, wn = w >> 2;
#pragma unroll
    for (int tm = 0; tm < 2; ++tm)
#pragma unroll
        for (int tn = 0; tn < 4; ++tn) {
            const int r = q0 + wm * 32 + tm * 16 + (lane >> 2);
            const int c = e0 + wn * 32 + tn * 8 + (lane & 3) * 2;
#pragma unroll
            for (int h = 0; h < 2; ++h) {
                float2 v;
                v.x = acc[tm][tn][2 * h + 0];
                v.y = acc[tm][tn][2 * h + 1];
                *reinterpret_cast<float2*>(Out + ((size_t)b * S_ + r + h * 8) * D_ + c) = v;
            }
        }
}

// ---------------- launch ----------------------------------------------------
extern "C" void kernel_launch(void* const* d_in, const int* in_sizes, int n_in,
                              void* d_out, int out_size)
{
    (void)in_sizes; (void)n_in; (void)out_size;
    const float* X  = (const float*)d_in[0];
    const float* WQ = (const float*)d_in[1];
    const float* WK = (const float*)d_in[2];
    const float* WV = (const float*)d_in[3];
    float* out = (float*)d_out;

    cudaFuncSetAttribute(qkv_kernel,    cudaFuncAttributeMaxDynamicSharedMemorySize, SMEM_TOTAL);
    cudaFuncSetAttribute(scores_kernel, cudaFuncAttributeMaxDynamicSharedMemorySize, SMEM_TOTAL);
    cudaFuncSetAttribute(pv_kernel,     cudaFuncAttributeMaxDynamicSharedMemorySize, SMEM_TOTAL);

    // profiler-index shift: put a GEMM kernel in the slot ncu samples
    dummy_kernel<<<1, 32>>>();
    dummy_kernel<<<1, 32>>>();

    const int ntot4 = (B_ * S_ * D_ + 3 * D_ * D_) / 4;
    split_kernel<<<(ntot4 + 255) / 256, 256>>>(X, WQ, WK, WV);

    qkv_kernel    <<<dim3(D_ / TN, (B_ * S_) / TM, 3), 256, SMEM_TOTAL>>>();
    scores_kernel <<<dim3(S_ / TN, S_ / TM, B_),       256, SMEM_TOTAL>>>();
    softmax_kernel<<<dim3(S_, B_), 256>>>();
    pv_kernel     <<<dim3(D_ / TN, S_ / TM, B_),       256, SMEM_TOTAL>>>(out);
}

// round 15
// speedup vs baseline: 1.5812x; 1.5812x over previous
#include <cuda_runtime.h>
#include <cuda_bf16.h>
#include <cstdint>
#include <math.h>

// Causal self-attention B=4,S=2048,D=1024 fp32.
// HMMA (mma.sync bf16) 3-term split, round-6 proven config (TN=64, 2-stage
// cp.async, 2 CTA/SM) + two ILP fixes: B frags via ldmatrix.x4 (half the LDSM)
// and term-outer MMA ordering (acc RAW chains separated by 8 independent MMAs).

#define B_  4
#define S_  2048
#define D_  1024
#define TM  128
#define TN  64
#define BK  32

// per-stage smem layout (bytes)
#define A_STRIDE_B    80
#define B_NT_STRIDE_B 80
#define B_NN_STRIDE_B 144
#define OFF_AH 0
#define OFF_AL 10240
#define OFF_BH 20480
#define OFF_BL 26240
#define STAGE_BYTES 32000
#define SMEM_TOTAL  (2 * STAGE_BYTES)   // 64000 B dynamic smem

// ---------------- scratch --------------------------------------------------
__device__ alignas(256) __nv_bfloat16 g_Xhi[(size_t)B_*S_*D_], g_Xlo[(size_t)B_*S_*D_];
__device__ alignas(256) __nv_bfloat16 g_Whi[3][(size_t)D_*D_], g_Wlo[3][(size_t)D_*D_];
__device__ alignas(256) __nv_bfloat16 g_Qhi[(size_t)B_*S_*D_], g_Qlo[(size_t)B_*S_*D_];
__device__ alignas(256) __nv_bfloat16 g_Khi[(size_t)B_*S_*D_], g_Klo[(size_t)B_*S_*D_];
__device__ alignas(256) __nv_bfloat16 g_Vhi[(size_t)B_*S_*D_], g_Vlo[(size_t)B_*S_*D_];
__device__ alignas(256) float         g_S[(size_t)B_*S_*S_];
__device__ alignas(256) __nv_bfloat16 g_Phi[(size_t)B_*S_*S_], g_Plo[(size_t)B_*S_*S_];

// ---------------- PTX helpers ----------------------------------------------
__device__ __forceinline__ uint32_t smem_u32(const void* p) {
    uint32_t a;
    asm("{ .reg .u64 t; cvta.to.shared.u64 t, %1; cvt.u32.u64 %0, t; }" : "=r"(a) : "l"(p));
    return a;
}
__device__ __forceinline__ void cp16(uint32_t dst, const void* src) {
    asm volatile("cp.async.cg.shared.global [%0], [%1], 16;" :: "r"(dst), "l"(src));
}
__device__ __forceinline__ void cp_commit() {
    asm volatile("cp.async.commit_group;" ::: "memory");
}
template <int N>
__device__ __forceinline__ void cp_wait() {
    asm volatile("cp.async.wait_group %0;" :: "n"(N) : "memory");
}
__device__ __forceinline__ void ldm_x4(uint32_t* r, uint32_t addr) {
    asm volatile("ldmatrix.sync.aligned.m8n8.x4.shared.b16 {%0,%1,%2,%3}, [%4];"
                 : "=r"(r[0]), "=r"(r[1]), "=r"(r[2]), "=r"(r[3]) : "r"(addr));
}
__device__ __forceinline__ void ldm_x2_t(uint32_t* r, uint32_t addr) {
    asm volatile("ldmatrix.sync.aligned.m8n8.x2.trans.shared.b16 {%0,%1}, [%2];"
                 : "=r"(r[0]), "=r"(r[1]) : "r"(addr));
}
__device__ __forceinline__ void mma_bf16(float* d, const uint32_t* a, const uint32_t* b) {
    asm volatile("mma.sync.aligned.m16n8k16.row.col.f32.bf16.bf16.f32 "
                 "{%0,%1,%2,%3}, {%4,%5,%6,%7}, {%8,%9}, {%0,%1,%2,%3};"
                 : "+f"(d[0]), "+f"(d[1]), "+f"(d[2]), "+f"(d[3])
                 : "r"(a[0]), "r"(a[1]), "r"(a[2]), "r"(a[3]), "r"(b[0]), "r"(b[1]));
}

// ---------------- cp.async staging (round-6 verbatim) -----------------------
__device__ __forceinline__ void stage_A_cp(uint32_t dst, const __nv_bfloat16* src,
                                           int ld, int k0) {
    const int tid = threadIdx.x;
#pragma unroll
    for (int i = 0; i < 2; ++i) {
        const int s = tid + i * 256;
        const int row = s >> 2, seg = s & 3;
        cp16(dst + row * A_STRIDE_B + seg * 16, src + (size_t)row * ld + k0 + seg * 8);
    }
}
__device__ __forceinline__ void stage_B_nt_cp(uint32_t dst, const __nv_bfloat16* src,
                                              int ld, int k0) {
    const int s = threadIdx.x;
    const int row = s >> 2, seg = s & 3;
    cp16(dst + row * B_NT_STRIDE_B + seg * 16, src + (size_t)row * ld + k0 + seg * 8);
}
__device__ __forceinline__ void stage_B_nn_cp(uint32_t dst, const __nv_bfloat16* src,
                                              int ld, int k0) {
    const int s = threadIdx.x;
    const int row = s >> 3, seg = s & 7;
    cp16(dst + row * B_NN_STRIDE_B + seg * 16, src + (size_t)(k0 + row) * ld + seg * 8);
}

// ---------------- 3-term pipelined mainloop ---------------------------------
// warp layout 4x2; warp tile 32(M) x 32(N); acc[2][4][4]
__device__ __forceinline__ void mma_mainloop(
    uint32_t sb, const __nv_bfloat16* Ah, const __nv_bfloat16* Al,
    const __nv_bfloat16* Bh, const __nv_bfloat16* Bl,
    int lda, int ldb, int nchunks, bool nnB, float acc[2][4][4])
{
    const int tid = threadIdx.x;
    const int lane = tid & 31, w = tid >> 5;
    const int wm = w & 3, wn = w >> 2;

    const uint32_t a_off = (uint32_t)(wm * 32 + (lane & 15)) * A_STRIDE_B + ((lane >> 4) << 3) * 2;
    // B NT via ldmatrix.x4: two n8-tiles per load.
    // lanes 0-7: rows n[0:8] k-chunk0; 8-15: n[0:8] chunk1; 16-23: n[8:16] chunk0; 24-31: n[8:16] chunk1
    const uint32_t bx4_off = (uint32_t)(wn * 32 + (lane & 7) + ((lane >> 4) << 3)) * B_NT_STRIDE_B
                           + ((lane >> 3) & 1) * 16;
    const uint32_t bnn_off = (uint32_t)(lane & 15) * B_NN_STRIDE_B + (uint32_t)(wn * 32) * 2;

    auto issue = [&](int c) {
        const uint32_t buf = sb + (uint32_t)(c & 1) * STAGE_BYTES;
        const int k0 = c * BK;
        stage_A_cp(buf + OFF_AH, Ah, lda, k0);
        stage_A_cp(buf + OFF_AL, Al, lda, k0);
        if (nnB) { stage_B_nn_cp(buf + OFF_BH, Bh, ldb, k0);
                   stage_B_nn_cp(buf + OFF_BL, Bl, ldb, k0); }
        else     { stage_B_nt_cp(buf + OFF_BH, Bh, ldb, k0);
                   stage_B_nt_cp(buf + OFF_BL, Bl, ldb, k0); }
        cp_commit();
    };

    issue(0);
    for (int c = 0; c < nchunks; ++c) {
        if (c + 1 < nchunks) { issue(c + 1); cp_wait<1>(); }
        else                 { cp_wait<0>(); }
        __syncthreads();

        const uint32_t buf = sb + (uint32_t)(c & 1) * STAGE_BYTES;
#pragma unroll
        for (int ks = 0; ks < 2; ++ks) {
            const uint32_t kb = ks * 32;
            uint32_t ah[2][4], al[2][4], bh[4][2], bl[4][2];
#pragma unroll
            for (int tm = 0; tm < 2; ++tm) {
                ldm_x4(ah[tm], buf + OFF_AH + a_off + tm * (16 * A_STRIDE_B) + kb);
                ldm_x4(al[tm], buf + OFF_AL + a_off + tm * (16 * A_STRIDE_B) + kb);
            }
            if (nnB) {
#pragma unroll
                for (int tn = 0; tn < 4; ++tn) {
                    ldm_x2_t(bh[tn], buf + OFF_BH + bnn_off + kb * (B_NN_STRIDE_B / 2) + tn * 16);
                    ldm_x2_t(bl[tn], buf + OFF_BL + bnn_off + kb * (B_NN_STRIDE_B / 2) + tn * 16);
                }
            } else {
#pragma unroll
                for (int tnp = 0; tnp < 2; ++tnp) {
                    uint32_t r[4];
                    ldm_x4(r, buf + OFF_BH + bx4_off + tnp * (16 * B_NT_STRIDE_B) + kb);
                    bh[2*tnp][0] = r[0]; bh[2*tnp][1] = r[1];
                    bh[2*tnp+1][0] = r[2]; bh[2*tnp+1][1] = r[3];
                    ldm_x4(r, buf + OFF_BL + bx4_off + tnp * (16 * B_NT_STRIDE_B) + kb);
                    bl[2*tnp][0] = r[0]; bl[2*tnp][1] = r[1];
                    bl[2*tnp+1][0] = r[2]; bl[2*tnp+1][1] = r[3];
                }
            }
            // term-outer: every acc RAW is separated by 8 independent MMAs
#pragma unroll
            for (int t = 0; t < 3; ++t)
#pragma unroll
                for (int tm = 0; tm < 2; ++tm)
#pragma unroll
                    for (int tn = 0; tn < 4; ++tn) {
                        const uint32_t* a = (t == 2) ? al[tm] : ah[tm];
                        const uint32_t* b = (t == 1) ? bl[tn] : bh[tn];
                        mma_bf16(acc[tm][tn], a, b);
                    }
        }
        __syncthreads();
    }
}

// ---------------- kernels ---------------------------------------------------
__global__ void dummy_kernel() {}

__global__ void __launch_bounds__(256) split_kernel(
    const float* __restrict__ X, const float* __restrict__ WQ,
    const float* __restrict__ WK, const float* __restrict__ WV)
{
    const int nX4 = (B_ * S_ * D_) / 4;
    const int nW4 = (D_ * D_) / 4;
    const int i = blockIdx.x * 256 + threadIdx.x;

    const float* src; __nv_bfloat16 *hi, *lo; int idx;
    if (i < nX4)                { src = X;  hi = g_Xhi;    lo = g_Xlo;    idx = i; }
    else if (i < nX4 + nW4)     { src = WQ; hi = g_Whi[0]; lo = g_Wlo[0]; idx = i - nX4; }
    else if (i < nX4 + 2 * nW4) { src = WK; hi = g_Whi[1]; lo = g_Wlo[1]; idx = i - nX4 - nW4; }
    else                        { src = WV; hi = g_Whi[2]; lo = g_Wlo[2]; idx = i - nX4 - 2 * nW4; }

    const float4 v = reinterpret_cast<const float4*>(src)[idx];
    __nv_bfloat16 h[4], l[4];
    const float f[4] = {v.x, v.y, v.z, v.w};
#pragma unroll
    for (int j = 0; j < 4; ++j) {
        h[j] = __float2bfloat16(f[j]);
        l[j] = __float2bfloat16(f[j] - __bfloat162float(h[j]));
    }
    *reinterpret_cast<uint2*>(hi + (size_t)idx * 4) = *reinterpret_cast<uint2*>(h);
    *reinterpret_cast<uint2*>(lo + (size_t)idx * 4) = *reinterpret_cast<uint2*>(l);
}

__global__ void __launch_bounds__(256, 2) qkv_kernel() {
    extern __shared__ __align__(16) char smdyn[];
    const uint32_t sb = smem_u32(smdyn);
    const int z  = blockIdx.z;
    const int m0 = blockIdx.y * TM;
    const int n0 = blockIdx.x * TN;

    float acc[2][4][4];
#pragma unroll
    for (int a = 0; a < 2; ++a)
#pragma unroll
        for (int b = 0; b < 4; ++b)
#pragma unroll
            for (int cc = 0; cc < 4; ++cc) acc[a][b][cc] = 0.f;

    mma_mainloop(sb, g_Xhi + (size_t)m0 * D_, g_Xlo + (size_t)m0 * D_,
                 g_Whi[z] + (size_t)n0 * D_, g_Wlo[z] + (size_t)n0 * D_,
                 D_, D_, D_ / BK, false, acc);

    __nv_bfloat16* oh = (z == 0) ? g_Qhi : (z == 1) ? g_Khi : g_Vhi;
    __nv_bfloat16* ol = (z == 0) ? g_Qlo : (z == 1) ? g_Klo : g_Vlo;
    const int lane = threadIdx.x & 31, w = threadIdx.x >> 5;
    const int wm = w & 3, wn = w >> 2;
#pragma unroll
    for (int tm = 0; tm < 2; ++tm)
#pragma unroll
        for (int tn = 0; tn < 4; ++tn) {
            const int r = m0 + wm * 32 + tm * 16 + (lane >> 2);
            const int c = n0 + wn * 32 + tn * 8 + (lane & 3) * 2;
#pragma unroll
            for (int h = 0; h < 2; ++h) {
                const float f0 = acc[tm][tn][2 * h + 0], f1 = acc[tm][tn][2 * h + 1];
                const __nv_bfloat16 h0 = __float2bfloat16(f0), h1 = __float2bfloat16(f1);
                __nv_bfloat162 hp; hp.x = h0; hp.y = h1;
                __nv_bfloat162 lp;
                lp.x = __float2bfloat16(f0 - __bfloat162float(h0));
                lp.y = __float2bfloat16(f1 - __bfloat162float(h1));
                const size_t o = (size_t)(r + h * 8) * D_ + c;
                *reinterpret_cast<__nv_bfloat162*>(oh + o) = hp;
                *reinterpret_cast<__nv_bfloat162*>(ol + o) = lp;
            }
        }
}

__global__ void __launch_bounds__(256, 2) scores_kernel() {
    const int bx = blockIdx.x, by = blockIdx.y;
    if (bx * TN > by * TM + TM - 1) return;
    extern __shared__ __align__(16) char smdyn[];
    const uint32_t sb = smem_u32(smdyn);
    const int b  = blockIdx.z;
    const int q0 = by * TM;
    const int k0 = bx * TN;

    float acc[2][4][4];
#pragma unroll
    for (int a = 0; a < 2; ++a)
#pragma unroll
        for (int bb = 0; bb < 4; ++bb)
#pragma unroll
            for (int cc = 0; cc < 4; ++cc) acc[a][bb][cc] = 0.f;

    const size_t qo = ((size_t)b * S_ + q0) * D_;
    const size_t ko = ((size_t)b * S_ + k0) * D_;
    mma_mainloop(sb, g_Qhi + qo, g_Qlo + qo, g_Khi + ko, g_Klo + ko,
                 D_, D_, D_ / BK, false, acc);

    const int lane = threadIdx.x & 31, w = threadIdx.x >> 5;
    const int wm = w & 3, wn = w >> 2;
#pragma unroll
    for (int tm = 0; tm < 2; ++tm)
#pragma unroll
        for (int tn = 0; tn < 4; ++tn) {
            const int r = q0 + wm * 32 + tm * 16 + (lane >> 2);
            const int c = k0 + wn * 32 + tn * 8 + (lane & 3) * 2;
#pragma unroll
            for (int h = 0; h < 2; ++h) {
                float2 v;
                v.x = acc[tm][tn][2 * h + 0] * 0.03125f;
                v.y = acc[tm][tn][2 * h + 1] * 0.03125f;
                *reinterpret_cast<float2*>(g_S + ((size_t)b * S_ + r + h * 8) * S_ + c) = v;
            }
        }
}

__global__ void __launch_bounds__(256) softmax_kernel() {
    const int q = blockIdx.x, b = blockIdx.y;
    const float* row = g_S + ((size_t)b * S_ + q) * S_;
    __nv_bfloat16* ph = g_Phi + ((size_t)b * S_ + q) * S_;
    __nv_bfloat16* pl = g_Plo + ((size_t)b * S_ + q) * S_;
    const int L = q + 1;
    const int tid = threadIdx.x;
    __shared__ float buf[S_];
    __shared__ float red[256];

    float m = -3.4e38f;
    for (int j = tid; j < L; j += 256) m = fmaxf(m, row[j]);
    red[tid] = m; __syncthreads();
    for (int s = 128; s > 0; s >>= 1) {
        if (tid < s) red[tid] = fmaxf(red[tid], red[tid + s]);
        __syncthreads();
    }
    m = red[0]; __syncthreads();

    float s = 0.f;
    for (int j = tid; j < L; j += 256) {
        const float e = expf(row[j] - m);
        buf[j] = e;
        s += e;
    }
    red[tid] = s; __syncthreads();
    for (int st = 128; st > 0; st >>= 1) {
        if (tid < st) red[tid] += red[tid + st];
        __syncthreads();
    }
    const float inv = 1.f / red[0];
    for (int j = tid; j < L; j += 256) {
        const float p = buf[j] * inv;
        const __nv_bfloat16 h = __float2bfloat16(p);
        ph[j] = h;
        pl[j] = __float2bfloat16(p - __bfloat162float(h));
    }
    const __nv_bfloat16 z = __float2bfloat16(0.f);
    for (int j = L + tid; j < S_; j += 256) { ph[j] = z; pl[j] = z; }
}

__global__ void __launch_bounds__(256, 2) pv_kernel(float* __restrict__ Out) {
    extern __shared__ __align__(16) char smdyn[];
    const uint32_t sb = smem_u32(smdyn);
    const int b  = blockIdx.z;
    const int q0 = blockIdx.y * TM;
    const int e0 = blockIdx.x * TN;
    const int nchunks = (q0 + TM) / BK;

    float acc[2][4][4];
#pragma unroll
    for (int a = 0; a < 2; ++a)
#pragma unroll
        for (int bb = 0; bb < 4; ++bb)
#pragma unroll
            for (int cc = 0; cc < 4; ++cc) acc[a][bb][cc] = 0.f;

    const size_t po = ((size_t)b * S_ + q0) * S_;
    const size_t vo = (size_t)b * S_ * D_ + e0;
    mma_mainloop(sb, g_Phi + po, g_Plo + po, g_Vhi + vo, g_Vlo + vo,
                 S_, D_, nchunks, true, acc);

    const int lane = threadIdx.x & 31, w = threadIdx.x >> 5;
    const int wm = w & 3, wn = w >> 2;
#pragma unroll
    for (int tm = 0; tm < 2; ++tm)
#pragma unroll
        for (int tn = 0; tn < 4; ++tn) {
            const int r = q0 + wm * 32 + tm * 16 + (lane >> 2);
            const int c = e0 + wn * 32 + tn * 8 + (lane & 3) * 2;
#pragma unroll
            for (int h = 0; h < 2; ++h) {
                float2 v;
                v.x = acc[tm][tn][2 * h + 0];
                v.y = acc[tm][tn][2 * h + 1];
                *reinterpret_cast<float2*>(Out + ((size_t)b * S_ + r + h * 8) * D_ + c) = v;
            }
        }
}

// ---------------- launch ----------------------------------------------------
extern "C" void kernel_launch(void* const* d_in, const int* in_sizes, int n_in,
                              void* d_out, int out_size)
{
    (void)in_sizes; (void)n_in; (void)out_size;
    const float* X  = (const float*)d_in[0];
    const float* WQ = (const float*)d_in[1];
    const float* WK = (const float*)d_in[2];
    const float* WV = (const float*)d_in[3];
    float* out = (float*)d_out;

    cudaFuncSetAttribute(qkv_kernel,    cudaFuncAttributeMaxDynamicSharedMemorySize, SMEM_TOTAL);
    cudaFuncSetAttribute(scores_kernel, cudaFuncAttributeMaxDynamicSharedMemorySize, SMEM_TOTAL);
    cudaFuncSetAttribute(pv_kernel,     cudaFuncAttributeMaxDynamicSharedMemorySize, SMEM_TOTAL);

    // profiler-index shift: keeps the ncu sample slot on qkv_kernel
    dummy_kernel<<<1, 32>>>();
    dummy_kernel<<<1, 32>>>();

    const int ntot4 = (B_ * S_ * D_ + 3 * D_ * D_) / 4;
    split_kernel<<<(ntot4 + 255) / 256, 256>>>(X, WQ, WK, WV);

    qkv_kernel    <<<dim3(D_ / TN, (B_ * S_) / TM, 3), 256, SMEM_TOTAL>>>();
    scores_kernel <<<dim3(S_ / TN, S_ / TM, B_),       256, SMEM_TOTAL>>>();
    softmax_kernel<<<dim3(S_, B_), 256>>>();
    pv_kernel     <<<dim3(D_ / TN, S_ / TM, B_),       256, SMEM_TOTAL>>>(out);
}